// round 1
// baseline (speedup 1.0000x reference)
#include <cuda_runtime.h>
#include <math.h>

#define NPIX 4096
#define BATCH 8
#define CH 64

// ---------------- scratch (device globals; no runtime allocation) ----------------
__device__ float g_featB[BATCH * 8 * NPIX];
__device__ float g_featC[BATCH * 8 * NPIX];
__device__ float g_featD[BATCH * CH * NPIX];
__device__ float g_xa[BATCH * CH * NPIX];
__device__ float g_xb[BATCH * CH * NPIX];
__device__ float g_attPart[16 * BATCH * CH * CH];
__device__ float g_attW[BATCH * CH * CH];
__device__ float g_conv[BATCH * 128 * NPIX];
__device__ float g_bnScale[128];
__device__ float g_bnShift[128];

// ---------------- K1: fused 1x1 projections (feat_b, feat_c, feat_d) ----------------
// grid (16, 5, 8), block 256. Each block computes 16 output rows over 256 pixels.
__global__ void k1_proj(const float* __restrict__ x,
                        const float* __restrict__ wb, const float* __restrict__ bb,
                        const float* __restrict__ wc, const float* __restrict__ bc,
                        const float* __restrict__ wd, const float* __restrict__ bd) {
    __shared__ float Ws[16][64];
    __shared__ float Bs[16];
    const int t = threadIdx.x;
    const int og0 = blockIdx.y * 16;
    const int b = blockIdx.z;

    for (int i = t; i < 16 * 64; i += 256) {
        int o = og0 + (i >> 6), c = i & 63;
        float w;
        if (o < 8) w = wb[o * 64 + c];
        else if (o < 16) w = wc[(o - 8) * 64 + c];
        else w = wd[(o - 16) * 64 + c];
        Ws[i >> 6][c] = w;
    }
    if (t < 16) {
        int o = og0 + t;
        Bs[t] = (o < 8) ? bb[o] : (o < 16) ? bc[o - 8] : bd[o - 16];
    }
    __syncthreads();

    const int n = blockIdx.x * 256 + t;
    const float* xp = x + (size_t)b * CH * NPIX + n;
    float acc[16];
#pragma unroll
    for (int i = 0; i < 16; i++) acc[i] = Bs[i];

    for (int c = 0; c < 64; c += 4) {
        float x0 = xp[(size_t)(c + 0) * NPIX];
        float x1 = xp[(size_t)(c + 1) * NPIX];
        float x2 = xp[(size_t)(c + 2) * NPIX];
        float x3 = xp[(size_t)(c + 3) * NPIX];
#pragma unroll
        for (int o = 0; o < 16; o++) {
            float4 w = *(const float4*)&Ws[o][c];
            acc[o] = fmaf(w.x, x0, fmaf(w.y, x1, fmaf(w.z, x2, fmaf(w.w, x3, acc[o]))));
        }
    }
#pragma unroll
    for (int o = 0; o < 16; o++) {
        int og = og0 + o;
        if (og < 8)       g_featB[(size_t)(b * 8 + og) * NPIX + n] = acc[o];
        else if (og < 16) g_featC[(size_t)(b * 8 + og - 8) * NPIX + n] = acc[o];
        else              g_featD[(size_t)(b * CH + og - 16) * NPIX + n] = acc[o];
    }
}

// ---------------- K2: PAM flash attention + alpha residual ----------------
// grid (32, 8), block 128. Thread = one query; keys streamed in 128-chunks.
// Logits are small (|S| < ~5) so exp without max-subtraction is safe/exact.
__global__ void __launch_bounds__(128) k2_pam(const float* __restrict__ x,
                                              const float* __restrict__ alpha) {
    __shared__ float Ks[8][128];
    __shared__ float Vs[64][128];
    const int t = threadIdx.x;
    const int b = blockIdx.y;
    const int n = blockIdx.x * 128 + t;

    float q[8];
#pragma unroll
    for (int d = 0; d < 8; d++) q[d] = g_featB[(size_t)(b * 8 + d) * NPIX + n];

    float acc[64];
#pragma unroll
    for (int c = 0; c < 64; c++) acc[c] = 0.f;
    float ssum = 0.f;

    const float4* fc4 = (const float4*)(g_featC + (size_t)b * 8 * NPIX);
    const float4* fd4 = (const float4*)(g_featD + (size_t)b * CH * NPIX);

    for (int mc = 0; mc < 32; mc++) {
        const int m04 = mc * 32;  // chunk start in float4 units
#pragma unroll
        for (int k = 0; k < 2; k++) {  // K tile: 8x128 = 256 float4
            int i = t + 128 * k;
            int d = i >> 5, col = i & 31;
            ((float4*)Ks[d])[col] = fc4[d * 1024 + m04 + col];
        }
#pragma unroll
        for (int k = 0; k < 16; k++) {  // V tile: 64x128 = 2048 float4
            int i = t + 128 * k;
            int c = i >> 5, col = i & 31;
            ((float4*)Vs[c])[col] = fd4[c * 1024 + m04 + col];
        }
        __syncthreads();

        for (int g = 0; g < 32; g++) {  // 4 keys per group
            float l0 = 0.f, l1 = 0.f, l2 = 0.f, l3 = 0.f;
#pragma unroll
            for (int d = 0; d < 8; d++) {
                float4 kv = ((const float4*)Ks[d])[g];
                l0 = fmaf(q[d], kv.x, l0);
                l1 = fmaf(q[d], kv.y, l1);
                l2 = fmaf(q[d], kv.z, l2);
                l3 = fmaf(q[d], kv.w, l3);
            }
            float p0 = __expf(l0), p1 = __expf(l1), p2 = __expf(l2), p3 = __expf(l3);
            ssum += (p0 + p1) + (p2 + p3);
#pragma unroll
            for (int c = 0; c < 64; c++) {
                float4 v = ((const float4*)Vs[c])[g];
                acc[c] = fmaf(p0, v.x, fmaf(p1, v.y, fmaf(p2, v.z, fmaf(p3, v.w, acc[c]))));
            }
        }
        __syncthreads();
    }

    const float sc = alpha[0] / ssum;
#pragma unroll
    for (int c = 0; c < 64; c++) {
        size_t idx = (size_t)(b * CH + c) * NPIX + n;
        g_xa[idx] = fmaf(sc, acc[c], x[idx]);
    }
}

// ---------------- K3: CAM Gram matrix partials (split over N, no atomics) ----------------
// grid (8, 16), block 256 (16x16 threads, each a 4x4 (c,d) tile).
__global__ void k3_att() {
    __shared__ float Xs[64][129];
    const int t = threadIdx.x;
    const int b = blockIdx.x;
    const int s = blockIdx.y;
    const int tx = t & 15, ty = t >> 4;

    float a4[4][4];
#pragma unroll
    for (int i = 0; i < 4; i++)
#pragma unroll
        for (int j = 0; j < 4; j++) a4[i][j] = 0.f;

    for (int chunk = 0; chunk < 2; chunk++) {
        const int n0 = s * 256 + chunk * 128;
        for (int i = t; i < 64 * 128; i += 256) {
            int c = i >> 7, col = i & 127;
            Xs[c][col] = g_xa[(size_t)(b * CH + c) * NPIX + n0 + col];
        }
        __syncthreads();
        for (int nn = 0; nn < 128; nn++) {
            float av[4], bv[4];
#pragma unroll
            for (int i = 0; i < 4; i++) av[i] = Xs[ty * 4 + i][nn];
#pragma unroll
            for (int j = 0; j < 4; j++) bv[j] = Xs[tx * 4 + j][nn];
#pragma unroll
            for (int i = 0; i < 4; i++)
#pragma unroll
                for (int j = 0; j < 4; j++) a4[i][j] = fmaf(av[i], bv[j], a4[i][j]);
        }
        __syncthreads();
    }
#pragma unroll
    for (int i = 0; i < 4; i++)
#pragma unroll
        for (int j = 0; j < 4; j++)
            g_attPart[(((size_t)s * BATCH + b) * CH + ty * 4 + i) * CH + tx * 4 + j] = a4[i][j];
}

// ---------------- K3b: reduce partials + CAM softmax(max-att) ----------------
// grid 8, block 64 (thread = row c).
__global__ void k3b_softmax() {
    const int b = blockIdx.x;
    const int c = threadIdx.x;
    float att[64];
#pragma unroll
    for (int d = 0; d < 64; d++) {
        float s = 0.f;
#pragma unroll
        for (int sp = 0; sp < 16; sp++)
            s += g_attPart[(((size_t)sp * BATCH + b) * CH + c) * CH + d];
        att[d] = s;
    }
    float rm = -3.4e38f, mn = 3.4e38f;
#pragma unroll
    for (int d = 0; d < 64; d++) { rm = fmaxf(rm, att[d]); mn = fminf(mn, att[d]); }
    // att_new = rm - att; its row max = rm - mn
    const float mx2 = rm - mn;
    float ssum = 0.f;
#pragma unroll
    for (int d = 0; d < 64; d++) {
        att[d] = __expf((rm - att[d]) - mx2);
        ssum += att[d];
    }
    const float inv = 1.f / ssum;
#pragma unroll
    for (int d = 0; d < 64; d++)
        g_attW[((size_t)b * CH + c) * CH + d] = att[d] * inv;
}

// ---------------- K4: CAM apply + beta residual ----------------
// grid (64, 8), block 256. n-tile of 64; thread = 2 channels x 8 pixels.
__global__ void k4_cam(const float* __restrict__ beta) {
    __shared__ float Xs[64][64];
    __shared__ float Ws[64][64];
    const int t = threadIdx.x;
    const int b = blockIdx.y;
    const int n0 = blockIdx.x * 64;

    for (int i = t; i < 64 * 64; i += 256) {
        int c = i >> 6, col = i & 63;
        Xs[c][col] = g_xa[(size_t)(b * CH + c) * NPIX + n0 + col];
        ((float*)Ws)[i] = g_attW[(size_t)b * CH * CH + i];
    }
    __syncthreads();

    const int tx = t & 7, ty = t >> 3;  // tx: 8 pixel groups, ty: 32 channel pairs
    float acc[2][8];
#pragma unroll
    for (int i = 0; i < 2; i++)
#pragma unroll
        for (int j = 0; j < 8; j++) acc[i][j] = 0.f;

    for (int d = 0; d < 64; d++) {
        float w0 = Ws[ty * 2 + 0][d];
        float w1 = Ws[ty * 2 + 1][d];
        float xv[8];
#pragma unroll
        for (int j = 0; j < 8; j++) xv[j] = Xs[d][tx * 8 + j];
#pragma unroll
        for (int j = 0; j < 8; j++) {
            acc[0][j] = fmaf(w0, xv[j], acc[0][j]);
            acc[1][j] = fmaf(w1, xv[j], acc[1][j]);
        }
    }
    const float be = beta[0];
#pragma unroll
    for (int i = 0; i < 2; i++) {
        int c = ty * 2 + i;
#pragma unroll
        for (int j = 0; j < 8; j++) {
            int nn = tx * 8 + j;
            g_xb[(size_t)(b * CH + c) * NPIX + n0 + nn] = fmaf(be, acc[i][j], Xs[c][nn]);
        }
    }
}

// ---------------- K5: conv3x3 (64->128), pad 1 ----------------
// grid (4, 32, 8), block 256 (16x16 threads, each 2x2 pixels x 4 out-channels).
__global__ void __launch_bounds__(256) k5_conv(const float* __restrict__ cw,
                                               const float* __restrict__ cb) {
    __shared__ float In[8][34][34];   // 37.0 KB
    __shared__ float Wt[4 * 64 * 9];  //  9.2 KB
    const int t = threadIdx.x;
    const int tile = blockIdx.x;           // 2x2 spatial tiles of 32x32
    const int ocg = blockIdx.y;            // groups of 4 out channels
    const int b = blockIdx.z;
    const int h0 = (tile >> 1) * 32;
    const int w0 = (tile & 1) * 32;
    const int tx = t & 15, ty = t >> 4;

    for (int i = t; i < 2304; i += 256) Wt[i] = cw[(size_t)ocg * 2304 + i];

    float acc[4][2][2];
#pragma unroll
    for (int o = 0; o < 4; o++)
#pragma unroll
        for (int a = 0; a < 2; a++)
#pragma unroll
            for (int bb2 = 0; bb2 < 2; bb2++) acc[o][a][bb2] = 0.f;

    for (int cc = 0; cc < 8; cc++) {
        __syncthreads();
        for (int i = t; i < 8 * 34 * 34; i += 256) {
            int ic = i / 1156;
            int rem = i - ic * 1156;
            int r = rem / 34, cl = rem - r * 34;
            int gh = h0 + r - 1, gw = w0 + cl - 1;
            float v = 0.f;
            if (gh >= 0 && gh < 64 && gw >= 0 && gw < 64)
                v = g_xb[(size_t)(b * CH + cc * 8 + ic) * NPIX + gh * 64 + gw];
            In[ic][r][cl] = v;
        }
        __syncthreads();
#pragma unroll
        for (int ic = 0; ic < 8; ic++) {
            float iv[4][4];
#pragma unroll
            for (int dy = 0; dy < 4; dy++)
#pragma unroll
                for (int dx = 0; dx < 4; dx++)
                    iv[dy][dx] = In[ic][ty * 2 + dy][tx * 2 + dx];
            const int icf = cc * 8 + ic;
#pragma unroll
            for (int o = 0; o < 4; o++) {
                const float* wp = &Wt[o * 576 + icf * 9];
#pragma unroll
                for (int ky = 0; ky < 3; ky++)
#pragma unroll
                    for (int kx = 0; kx < 3; kx++) {
                        float wv = wp[ky * 3 + kx];
                        acc[o][0][0] = fmaf(wv, iv[ky + 0][kx + 0], acc[o][0][0]);
                        acc[o][0][1] = fmaf(wv, iv[ky + 0][kx + 1], acc[o][0][1]);
                        acc[o][1][0] = fmaf(wv, iv[ky + 1][kx + 0], acc[o][1][0]);
                        acc[o][1][1] = fmaf(wv, iv[ky + 1][kx + 1], acc[o][1][1]);
                    }
            }
        }
    }
#pragma unroll
    for (int o = 0; o < 4; o++) {
        const int oc = ocg * 4 + o;
        const float bs = cb[oc];
#pragma unroll
        for (int a = 0; a < 2; a++)
#pragma unroll
            for (int bb2 = 0; bb2 < 2; bb2++) {
                int hh = h0 + ty * 2 + a, ww = w0 + tx * 2 + bb2;
                g_conv[(size_t)(b * 128 + oc) * NPIX + hh * 64 + ww] = acc[o][a][bb2] + bs;
            }
    }
}

// ---------------- K5b: BN stats per channel -> scale/shift ----------------
// grid 128, block 256. Block owns one full channel (8*4096 values).
__global__ void k5b_bn(const float* __restrict__ gamma, const float* __restrict__ bbeta) {
    const int oc = blockIdx.x;
    const int t = threadIdx.x;
    float s = 0.f, sq = 0.f;
    for (int i = t; i < BATCH * NPIX; i += 256) {
        int bb = i >> 12, hw = i & 4095;
        float v = g_conv[(size_t)(bb * 128 + oc) * NPIX + hw];
        s += v;
        sq += v * v;
    }
    __shared__ float rs[256], rq[256];
    rs[t] = s; rq[t] = sq;
    __syncthreads();
    for (int st = 128; st > 0; st >>= 1) {
        if (t < st) { rs[t] += rs[t + st]; rq[t] += rq[t + st]; }
        __syncthreads();
    }
    if (t == 0) {
        const float invN = 1.f / (BATCH * NPIX);
        float mean = rs[0] * invN;
        float var = rq[0] * invN - mean * mean;
        float sc = gamma[oc] * rsqrtf(var + 1e-5f);
        g_bnScale[oc] = sc;
        g_bnShift[oc] = bbeta[oc] - mean * sc;
    }
}

// ---------------- K7: BN apply + ReLU + maxpool(2,2, h-pad 1) ----------------
// Output [8,128,33,32]. Affine applied before max (scale sign-safe).
__global__ void k7_pool(float* __restrict__ out) {
    const int idx = blockIdx.x * 256 + threadIdx.x;
    const int TOT = BATCH * 128 * 33 * 32;
    if (idx >= TOT) return;
    int pw = idx & 31;
    int tmp = idx >> 5;
    int ph = tmp % 33; tmp /= 33;
    int oc = tmp & 127;
    int b = tmp >> 7;

    const float sc = g_bnScale[oc], sh = g_bnShift[oc];
    const float* base = g_conv + (size_t)(b * 128 + oc) * NPIX;
    const int w1 = pw * 2;
    const int h1 = ph * 2 - 1;
    float m = -3.4e38f;
#pragma unroll
    for (int k = 0; k < 2; k++) {
        int hh = h1 + k;
        if (hh < 0 || hh >= 64) continue;
        m = fmaxf(m, fmaf(base[hh * 64 + w1], sc, sh));
        m = fmaxf(m, fmaf(base[hh * 64 + w1 + 1], sc, sh));
    }
    out[idx] = fmaxf(m, 0.f);
}

// ---------------- launch ----------------
extern "C" void kernel_launch(void* const* d_in, const int* in_sizes, int n_in,
                              void* d_out, int out_size) {
    const float* x     = (const float*)d_in[0];
    const float* wb    = (const float*)d_in[1];
    const float* bb    = (const float*)d_in[2];
    const float* wc    = (const float*)d_in[3];
    const float* bc    = (const float*)d_in[4];
    const float* wd    = (const float*)d_in[5];
    const float* bd    = (const float*)d_in[6];
    const float* alpha = (const float*)d_in[7];
    const float* beta  = (const float*)d_in[8];
    const float* cw    = (const float*)d_in[9];
    const float* cb    = (const float*)d_in[10];
    const float* gamma = (const float*)d_in[11];
    const float* bbeta = (const float*)d_in[12];
    float* out = (float*)d_out;

    k1_proj<<<dim3(16, 5, 8), 256>>>(x, wb, bb, wc, bc, wd, bd);
    k2_pam<<<dim3(32, 8), 128>>>(x, alpha);
    k3_att<<<dim3(8, 16), 256>>>();
    k3b_softmax<<<8, 64>>>();
    k4_cam<<<dim3(64, 8), 256>>>(beta);
    k5_conv<<<dim3(4, 32, 8), 256>>>(cw, cb);
    k5b_bn<<<128, 256>>>(gamma, bbeta);
    const int tot = BATCH * 128 * 33 * 32;
    k7_pool<<<(tot + 255) / 256, 256>>>(out);
}

// round 2
// speedup vs baseline: 1.0805x; 1.0805x over previous
#include <cuda_runtime.h>
#include <math.h>

#define NPIX 4096
#define BATCH 8
#define CH 64

typedef unsigned long long u64;

// ---------------- f32x2 helpers (Blackwell packed fp32) ----------------
__device__ __forceinline__ u64 pk2(float lo, float hi) {
    u64 r; asm("mov.b64 %0, {%1, %2};" : "=l"(r) : "f"(lo), "f"(hi)); return r;
}
__device__ __forceinline__ void upk2(u64 v, float& lo, float& hi) {
    asm("mov.b64 {%0, %1}, %2;" : "=f"(lo), "=f"(hi) : "l"(v));
}
__device__ __forceinline__ u64 ffma2(u64 a, u64 b, u64 c) {
    u64 d; asm("fma.rn.f32x2 %0, %1, %2, %3;" : "=l"(d) : "l"(a), "l"(b), "l"(c)); return d;
}
union V4 { float4 f; u64 u[2]; };
union F2 { float2 f; u64 u; };

// ---------------- scratch (device globals) ----------------
__device__ float g_featB[BATCH * 8 * NPIX];
__device__ float g_featC[BATCH * 8 * NPIX];
__device__ float g_featD[BATCH * CH * NPIX];
__device__ float g_featDT[BATCH * NPIX * CH];   // key-major V
__device__ float g_xa[BATCH * CH * NPIX];
__device__ float g_xb[BATCH * CH * NPIX];
__device__ float g_attPart[16 * BATCH * CH * CH];
__device__ float g_attW[BATCH * CH * CH];
__device__ float g_conv[BATCH * 128 * NPIX];
__device__ float g_bnScale[128];
__device__ float g_bnShift[128];
__device__ float2 g_cw2[128 * 576];             // duplicated conv weights

// ---------------- K1: fused 1x1 projections ----------------
__global__ void k1_proj(const float* __restrict__ x,
                        const float* __restrict__ wb, const float* __restrict__ bb,
                        const float* __restrict__ wc, const float* __restrict__ bc,
                        const float* __restrict__ wd, const float* __restrict__ bd) {
    __shared__ float Ws[16][64];
    __shared__ float Bs[16];
    const int t = threadIdx.x;
    const int og0 = blockIdx.y * 16;
    const int b = blockIdx.z;

    for (int i = t; i < 16 * 64; i += 256) {
        int o = og0 + (i >> 6), c = i & 63;
        float w;
        if (o < 8) w = wb[o * 64 + c];
        else if (o < 16) w = wc[(o - 8) * 64 + c];
        else w = wd[(o - 16) * 64 + c];
        Ws[i >> 6][c] = w;
    }
    if (t < 16) {
        int o = og0 + t;
        Bs[t] = (o < 8) ? bb[o] : (o < 16) ? bc[o - 8] : bd[o - 16];
    }
    __syncthreads();

    const int n = blockIdx.x * 256 + t;
    const float* xp = x + (size_t)b * CH * NPIX + n;
    float acc[16];
#pragma unroll
    for (int i = 0; i < 16; i++) acc[i] = Bs[i];

    for (int c = 0; c < 64; c += 4) {
        float x0 = xp[(size_t)(c + 0) * NPIX];
        float x1 = xp[(size_t)(c + 1) * NPIX];
        float x2 = xp[(size_t)(c + 2) * NPIX];
        float x3 = xp[(size_t)(c + 3) * NPIX];
#pragma unroll
        for (int o = 0; o < 16; o++) {
            float4 w = *(const float4*)&Ws[o][c];
            acc[o] = fmaf(w.x, x0, fmaf(w.y, x1, fmaf(w.z, x2, fmaf(w.w, x3, acc[o]))));
        }
    }
#pragma unroll
    for (int o = 0; o < 16; o++) {
        int og = og0 + o;
        if (og < 8)       g_featB[(size_t)(b * 8 + og) * NPIX + n] = acc[o];
        else if (og < 16) g_featC[(size_t)(b * 8 + og - 8) * NPIX + n] = acc[o];
        else              g_featD[(size_t)(b * CH + og - 16) * NPIX + n] = acc[o];
    }
}

// ---------------- K1t: transpose featD [b][c][n] -> featDT [b][n][c] ----------------
__global__ void k1t_transpose() {
    __shared__ float tile[64][65];
    const int t = threadIdx.x;
    const int b = blockIdx.y;
    const int n0 = blockIdx.x * 64;
#pragma unroll
    for (int k = 0; k < 16; k++) {
        int i = t + 256 * k;
        int c = i >> 6, nn = i & 63;
        tile[c][nn] = g_featD[(size_t)(b * CH + c) * NPIX + n0 + nn];
    }
    __syncthreads();
#pragma unroll
    for (int k = 0; k < 16; k++) {
        int i = t + 256 * k;
        int nn = i >> 6, c = i & 63;
        g_featDT[((size_t)b * NPIX + n0 + nn) * CH + c] = tile[c][nn];
    }
}

// ---------------- K2: PAM flash attention (f32x2) + alpha residual ----------------
// grid (16, 8), block 256. Thread = one query. V key-major in smem.
__global__ void __launch_bounds__(256) k2_pam(const float* __restrict__ x,
                                              const float* __restrict__ alpha) {
    __shared__ float Ks[8][128];    // [dim][key]
    __shared__ float Vs[128][64];   // [key][channel]
    const int t = threadIdx.x;
    const int b = blockIdx.y;
    const int n = blockIdx.x * 256 + t;

    u64 q2[8];
#pragma unroll
    for (int d = 0; d < 8; d++) {
        float qv = g_featB[(size_t)(b * 8 + d) * NPIX + n];
        q2[d] = pk2(qv, qv);
    }

    u64 acc2[32];
#pragma unroll
    for (int c = 0; c < 32; c++) acc2[c] = 0ull;
    float ssum = 0.f;

    const float4* fc4 = (const float4*)(g_featC + (size_t)b * 8 * NPIX);
    const float4* fdt4 = (const float4*)(g_featDT + (size_t)b * NPIX * CH);

    for (int mc = 0; mc < 32; mc++) {
        const int m04 = mc * 32;   // chunk start, float4 units over keys
        const int m0 = mc * 128;   // chunk start, key units
        {   // K tile: 8x128 = 256 float4, 1 per thread
            int d = t >> 5, col = t & 31;
            ((float4*)Ks[d])[col] = fc4[d * 1024 + m04 + col];
        }
#pragma unroll
        for (int k = 0; k < 8; k++) {  // V tile: 128x64 = 2048 float4
            int i = t + 256 * k;
            int row = i >> 4, cq = i & 15;
            ((float4*)Vs[row])[cq] = fdt4[(size_t)(m0 + row) * 16 + cq];
        }
        __syncthreads();

        for (int g = 0; g < 32; g++) {  // 4 keys per group
            u64 l01 = 0ull, l23 = 0ull;
#pragma unroll
            for (int d = 0; d < 8; d++) {
                V4 kk; kk.f = ((const float4*)Ks[d])[g];
                l01 = ffma2(q2[d], kk.u[0], l01);
                l23 = ffma2(q2[d], kk.u[1], l23);
            }
            float l0, l1, l2, l3;
            upk2(l01, l0, l1); upk2(l23, l2, l3);
            float p0 = __expf(l0), p1 = __expf(l1), p2 = __expf(l2), p3 = __expf(l3);
            ssum += (p0 + p1) + (p2 + p3);
            u64 P[4] = {pk2(p0, p0), pk2(p1, p1), pk2(p2, p2), pk2(p3, p3)};
#pragma unroll
            for (int j = 0; j < 4; j++) {
                const float4* vp = (const float4*)Vs[4 * g + j];
#pragma unroll
                for (int cq = 0; cq < 16; cq++) {
                    V4 vv; vv.f = vp[cq];
                    acc2[2 * cq]     = ffma2(P[j], vv.u[0], acc2[2 * cq]);
                    acc2[2 * cq + 1] = ffma2(P[j], vv.u[1], acc2[2 * cq + 1]);
                }
            }
        }
        __syncthreads();
    }

    const float sc = alpha[0] / ssum;
#pragma unroll
    for (int cq = 0; cq < 32; cq++) {
        float a0, a1;
        upk2(acc2[cq], a0, a1);
        size_t i0 = (size_t)(b * CH + 2 * cq) * NPIX + n;
        g_xa[i0] = fmaf(sc, a0, x[i0]);
        g_xa[i0 + NPIX] = fmaf(sc, a1, x[i0 + NPIX]);
    }
}

// ---------------- K3: CAM Gram matrix partials ----------------
__global__ void k3_att() {
    __shared__ float Xs[64][129];
    const int t = threadIdx.x;
    const int b = blockIdx.x;
    const int s = blockIdx.y;
    const int tx = t & 15, ty = t >> 4;

    float a4[4][4];
#pragma unroll
    for (int i = 0; i < 4; i++)
#pragma unroll
        for (int j = 0; j < 4; j++) a4[i][j] = 0.f;

    for (int chunk = 0; chunk < 2; chunk++) {
        const int n0 = s * 256 + chunk * 128;
        for (int i = t; i < 64 * 128; i += 256) {
            int c = i >> 7, col = i & 127;
            Xs[c][col] = g_xa[(size_t)(b * CH + c) * NPIX + n0 + col];
        }
        __syncthreads();
        for (int nn = 0; nn < 128; nn++) {
            float av[4], bv[4];
#pragma unroll
            for (int i = 0; i < 4; i++) av[i] = Xs[ty * 4 + i][nn];
#pragma unroll
            for (int j = 0; j < 4; j++) bv[j] = Xs[tx * 4 + j][nn];
#pragma unroll
            for (int i = 0; i < 4; i++)
#pragma unroll
                for (int j = 0; j < 4; j++) a4[i][j] = fmaf(av[i], bv[j], a4[i][j]);
        }
        __syncthreads();
    }
#pragma unroll
    for (int i = 0; i < 4; i++)
#pragma unroll
        for (int j = 0; j < 4; j++)
            g_attPart[(((size_t)s * BATCH + b) * CH + ty * 4 + i) * CH + tx * 4 + j] = a4[i][j];
}

// ---------------- K3b: reduce partials + CAM softmax (parallel) ----------------
// grid (64, 8), block 64. Block = (c, b); thread = d.
__global__ void k3b_softmax() {
    const int c = blockIdx.x;
    const int b = blockIdx.y;
    const int d = threadIdx.x;
    const int lane = d & 31, warp = d >> 5;

    float s = 0.f;
#pragma unroll
    for (int sp = 0; sp < 16; sp++)
        s += g_attPart[(((size_t)sp * BATCH + b) * CH + c) * CH + d];

    // row min across 64 threads (softmax of (rowmax - att) needs only min)
    float mn = s;
#pragma unroll
    for (int off = 16; off > 0; off >>= 1)
        mn = fminf(mn, __shfl_xor_sync(0xFFFFFFFFu, mn, off));
    __shared__ float sm2[2], ss2[2];
    if (lane == 0) sm2[warp] = mn;
    __syncthreads();
    mn = fminf(sm2[0], sm2[1]);

    float p = __expf(mn - s);
    float ps = p;
#pragma unroll
    for (int off = 16; off > 0; off >>= 1)
        ps += __shfl_xor_sync(0xFFFFFFFFu, ps, off);
    if (lane == 0) ss2[warp] = ps;
    __syncthreads();
    const float inv = 1.f / (ss2[0] + ss2[1]);
    g_attW[((size_t)b * CH + c) * CH + d] = p * inv;
}

// ---------------- K4: CAM apply + beta residual ----------------
__global__ void k4_cam(const float* __restrict__ beta) {
    __shared__ float Xs[64][64];
    __shared__ float Ws[64][64];
    const int t = threadIdx.x;
    const int b = blockIdx.y;
    const int n0 = blockIdx.x * 64;

    for (int i = t; i < 64 * 64; i += 256) {
        int c = i >> 6, col = i & 63;
        Xs[c][col] = g_xa[(size_t)(b * CH + c) * NPIX + n0 + col];
        ((float*)Ws)[i] = g_attW[(size_t)b * CH * CH + i];
    }
    __syncthreads();

    const int tx = t & 7, ty = t >> 3;
    float acc[2][8];
#pragma unroll
    for (int i = 0; i < 2; i++)
#pragma unroll
        for (int j = 0; j < 8; j++) acc[i][j] = 0.f;

    for (int d = 0; d < 64; d++) {
        float w0 = Ws[ty * 2 + 0][d];
        float w1 = Ws[ty * 2 + 1][d];
        float xv[8];
#pragma unroll
        for (int j = 0; j < 8; j++) xv[j] = Xs[d][tx * 8 + j];
#pragma unroll
        for (int j = 0; j < 8; j++) {
            acc[0][j] = fmaf(w0, xv[j], acc[0][j]);
            acc[1][j] = fmaf(w1, xv[j], acc[1][j]);
        }
    }
    const float be = beta[0];
#pragma unroll
    for (int i = 0; i < 2; i++) {
        int c = ty * 2 + i;
#pragma unroll
        for (int j = 0; j < 8; j++) {
            int nn = tx * 8 + j;
            g_xb[(size_t)(b * CH + c) * NPIX + n0 + nn] = fmaf(be, acc[i][j], Xs[c][nn]);
        }
    }
}

// ---------------- K5w: duplicate conv weights to float2 ----------------
__global__ void k5w_dup(const float* __restrict__ cw) {
    int i = blockIdx.x * 256 + threadIdx.x;
    if (i < 128 * 576) {
        float w = cw[i];
        g_cw2[i] = make_float2(w, w);
    }
}

// ---------------- K5: conv3x3 (64->128), f32x2, pad 1 ----------------
// grid (4, 32, 8), block 256 (16x16 threads, 2x2 pixels x 4 out-channels).
__global__ void __launch_bounds__(256) k5_conv(const float* __restrict__ cb) {
    __shared__ float In[4][34][34];      // 18.1 KB
    __shared__ float2 Wt2[4 * 576];      // 18.4 KB
    const int t = threadIdx.x;
    const int tile = blockIdx.x;
    const int ocg = blockIdx.y;
    const int b = blockIdx.z;
    const int h0 = (tile >> 1) * 32;
    const int w0 = (tile & 1) * 32;
    const int tx = t & 15, ty = t >> 4;

    for (int i = t; i < 2304; i += 256) Wt2[i] = g_cw2[(size_t)ocg * 2304 + i];

    u64 acc2[4][2];
#pragma unroll
    for (int o = 0; o < 4; o++) { acc2[o][0] = 0ull; acc2[o][1] = 0ull; }

    for (int cc = 0; cc < 16; cc++) {   // 16 chunks of 4 input channels
        __syncthreads();
        for (int i = t; i < 4 * 34 * 34; i += 256) {
            int ic = i / 1156;
            int rem = i - ic * 1156;
            int r = rem / 34, cl = rem - r * 34;
            int gh = h0 + r - 1, gw = w0 + cl - 1;
            float v = 0.f;
            if (gh >= 0 && gh < 64 && gw >= 0 && gw < 64)
                v = g_xb[(size_t)(b * CH + cc * 4 + ic) * NPIX + gh * 64 + gw];
            In[ic][r][cl] = v;
        }
        __syncthreads();
#pragma unroll
        for (int ic = 0; ic < 4; ic++) {
            u64 xa[4], xb2[4], xm[4];
#pragma unroll
            for (int dy = 0; dy < 4; dy++) {
                F2 A, Bv;
                A.f  = *(const float2*)&In[ic][ty * 2 + dy][tx * 2];
                Bv.f = *(const float2*)&In[ic][ty * 2 + dy][tx * 2 + 2];
                xa[dy] = A.u;
                xb2[dy] = Bv.u;
                xm[dy] = pk2(A.f.y, Bv.f.x);
            }
            const int icf = cc * 4 + ic;
#pragma unroll
            for (int o = 0; o < 4; o++) {
                const float2* wp = &Wt2[o * 576 + icf * 9];
#pragma unroll
                for (int ky = 0; ky < 3; ky++)
#pragma unroll
                    for (int kx = 0; kx < 3; kx++) {
                        F2 w; w.f = wp[ky * 3 + kx];
                        const u64* xrow = (kx == 0) ? xa : (kx == 1) ? xm : xb2;
                        acc2[o][0] = ffma2(w.u, xrow[ky + 0], acc2[o][0]);
                        acc2[o][1] = ffma2(w.u, xrow[ky + 1], acc2[o][1]);
                    }
            }
        }
    }
#pragma unroll
    for (int o = 0; o < 4; o++) {
        const int oc = ocg * 4 + o;
        const float bs = cb[oc];
#pragma unroll
        for (int a = 0; a < 2; a++) {
            float r0, r1;
            upk2(acc2[o][a], r0, r1);
            int hh = h0 + ty * 2 + a, ww = w0 + tx * 2;
            size_t base = (size_t)(b * 128 + oc) * NPIX + hh * 64 + ww;
            g_conv[base] = r0 + bs;
            g_conv[base + 1] = r1 + bs;
        }
    }
}

// ---------------- K5b: BN stats per channel ----------------
__global__ void k5b_bn(const float* __restrict__ gamma, const float* __restrict__ bbeta) {
    const int oc = blockIdx.x;
    const int t = threadIdx.x;
    float s = 0.f, sq = 0.f;
    for (int i = t; i < BATCH * NPIX; i += 256) {
        int bb = i >> 12, hw = i & 4095;
        float v = g_conv[(size_t)(bb * 128 + oc) * NPIX + hw];
        s += v;
        sq += v * v;
    }
    __shared__ float rs[256], rq[256];
    rs[t] = s; rq[t] = sq;
    __syncthreads();
    for (int st = 128; st > 0; st >>= 1) {
        if (t < st) { rs[t] += rs[t + st]; rq[t] += rq[t + st]; }
        __syncthreads();
    }
    if (t == 0) {
        const float invN = 1.f / (BATCH * NPIX);
        float mean = rs[0] * invN;
        float var = rq[0] * invN - mean * mean;
        float sc = gamma[oc] * rsqrtf(var + 1e-5f);
        g_bnScale[oc] = sc;
        g_bnShift[oc] = bbeta[oc] - mean * sc;
    }
}

// ---------------- K7: BN apply + ReLU + maxpool(2,2, h-pad 1) ----------------
__global__ void k7_pool(float* __restrict__ out) {
    const int idx = blockIdx.x * 256 + threadIdx.x;
    const int TOT = BATCH * 128 * 33 * 32;
    if (idx >= TOT) return;
    int pw = idx & 31;
    int tmp = idx >> 5;
    int ph = tmp % 33; tmp /= 33;
    int oc = tmp & 127;
    int b = tmp >> 7;

    const float sc = g_bnScale[oc], sh = g_bnShift[oc];
    const float* base = g_conv + (size_t)(b * 128 + oc) * NPIX;
    const int w1 = pw * 2;
    const int h1 = ph * 2 - 1;
    float m = -3.4e38f;
#pragma unroll
    for (int k = 0; k < 2; k++) {
        int hh = h1 + k;
        if (hh < 0 || hh >= 64) continue;
        m = fmaxf(m, fmaf(base[hh * 64 + w1], sc, sh));
        m = fmaxf(m, fmaf(base[hh * 64 + w1 + 1], sc, sh));
    }
    out[idx] = fmaxf(m, 0.f);
}

// ---------------- launch ----------------
extern "C" void kernel_launch(void* const* d_in, const int* in_sizes, int n_in,
                              void* d_out, int out_size) {
    const float* x     = (const float*)d_in[0];
    const float* wb    = (const float*)d_in[1];
    const float* bb    = (const float*)d_in[2];
    const float* wc    = (const float*)d_in[3];
    const float* bc    = (const float*)d_in[4];
    const float* wd    = (const float*)d_in[5];
    const float* bd    = (const float*)d_in[6];
    const float* alpha = (const float*)d_in[7];
    const float* beta  = (const float*)d_in[8];
    const float* cw    = (const float*)d_in[9];
    const float* cb    = (const float*)d_in[10];
    const float* gamma = (const float*)d_in[11];
    const float* bbeta = (const float*)d_in[12];
    float* out = (float*)d_out;

    k5w_dup<<<(128 * 576 + 255) / 256, 256>>>(cw);
    k1_proj<<<dim3(16, 5, 8), 256>>>(x, wb, bb, wc, bc, wd, bd);
    k1t_transpose<<<dim3(64, 8), 256>>>();
    k2_pam<<<dim3(16, 8), 256>>>(x, alpha);
    k3_att<<<dim3(8, 16), 256>>>();
    k3b_softmax<<<dim3(64, 8), 64>>>();
    k4_cam<<<dim3(64, 8), 256>>>(beta);
    k5_conv<<<dim3(4, 32, 8), 256>>>(cb);
    k5b_bn<<<128, 256>>>(gamma, bbeta);
    const int tot = BATCH * 128 * 33 * 32;
    k7_pool<<<(tot + 255) / 256, 256>>>(out);
}

// round 3
// speedup vs baseline: 1.1557x; 1.0695x over previous
#include <cuda_runtime.h>
#include <math.h>

#define NPIX 4096
#define BATCH 8
#define CH 64

typedef unsigned long long u64;

// ---------------- f32x2 helpers (Blackwell packed fp32) ----------------
__device__ __forceinline__ u64 pk2(float lo, float hi) {
    u64 r; asm("mov.b64 %0, {%1, %2};" : "=l"(r) : "f"(lo), "f"(hi)); return r;
}
__device__ __forceinline__ void upk2(u64 v, float& lo, float& hi) {
    asm("mov.b64 {%0, %1}, %2;" : "=f"(lo), "=f"(hi) : "l"(v));
}
__device__ __forceinline__ u64 ffma2(u64 a, u64 b, u64 c) {
    u64 d; asm("fma.rn.f32x2 %0, %1, %2, %3;" : "=l"(d) : "l"(a), "l"(b), "l"(c)); return d;
}
union V4 { float4 f; u64 u[2]; };
union F2 { float2 f; u64 u; };

// ---------------- scratch (device globals) ----------------
__device__ float g_featB[BATCH * 8 * NPIX];
__device__ float g_featC[BATCH * 8 * NPIX];
__device__ float g_featD[BATCH * CH * NPIX];
__device__ float g_featDT[BATCH * NPIX * CH];   // key-major V
__device__ float g_xa[BATCH * CH * NPIX];
__device__ float g_xb[BATCH * CH * NPIX];
__device__ float g_attPart[16 * BATCH * CH * CH];
__device__ float g_attW[BATCH * CH * CH];
__device__ float g_conv[BATCH * 128 * NPIX];
__device__ float g_bnScale[128];
__device__ float g_bnShift[128];
__device__ float2 g_cw2[128 * 576];             // duplicated conv weights

// ---------------- K1: fused 1x1 projections ----------------
__global__ void k1_proj(const float* __restrict__ x,
                        const float* __restrict__ wb, const float* __restrict__ bb,
                        const float* __restrict__ wc, const float* __restrict__ bc,
                        const float* __restrict__ wd, const float* __restrict__ bd) {
    __shared__ float Ws[16][64];
    __shared__ float Bs[16];
    const int t = threadIdx.x;
    const int og0 = blockIdx.y * 16;
    const int b = blockIdx.z;

    for (int i = t; i < 16 * 64; i += 256) {
        int o = og0 + (i >> 6), c = i & 63;
        float w;
        if (o < 8) w = wb[o * 64 + c];
        else if (o < 16) w = wc[(o - 8) * 64 + c];
        else w = wd[(o - 16) * 64 + c];
        Ws[i >> 6][c] = w;
    }
    if (t < 16) {
        int o = og0 + t;
        Bs[t] = (o < 8) ? bb[o] : (o < 16) ? bc[o - 8] : bd[o - 16];
    }
    __syncthreads();

    const int n = blockIdx.x * 256 + t;
    const float* xp = x + (size_t)b * CH * NPIX + n;
    float acc[16];
#pragma unroll
    for (int i = 0; i < 16; i++) acc[i] = Bs[i];

    for (int c = 0; c < 64; c += 4) {
        float x0 = xp[(size_t)(c + 0) * NPIX];
        float x1 = xp[(size_t)(c + 1) * NPIX];
        float x2 = xp[(size_t)(c + 2) * NPIX];
        float x3 = xp[(size_t)(c + 3) * NPIX];
#pragma unroll
        for (int o = 0; o < 16; o++) {
            float4 w = *(const float4*)&Ws[o][c];
            acc[o] = fmaf(w.x, x0, fmaf(w.y, x1, fmaf(w.z, x2, fmaf(w.w, x3, acc[o]))));
        }
    }
#pragma unroll
    for (int o = 0; o < 16; o++) {
        int og = og0 + o;
        if (og < 8)       g_featB[(size_t)(b * 8 + og) * NPIX + n] = acc[o];
        else if (og < 16) g_featC[(size_t)(b * 8 + og - 8) * NPIX + n] = acc[o];
        else              g_featD[(size_t)(b * CH + og - 16) * NPIX + n] = acc[o];
    }
}

// ---------------- K1t: transpose featD [b][c][n] -> featDT [b][n][c] ----------------
__global__ void k1t_transpose() {
    __shared__ float tile[64][65];
    const int t = threadIdx.x;
    const int b = blockIdx.y;
    const int n0 = blockIdx.x * 64;
#pragma unroll
    for (int k = 0; k < 16; k++) {
        int i = t + 256 * k;
        int c = i >> 6, nn = i & 63;
        tile[c][nn] = g_featD[(size_t)(b * CH + c) * NPIX + n0 + nn];
    }
    __syncthreads();
#pragma unroll
    for (int k = 0; k < 16; k++) {
        int i = t + 256 * k;
        int nn = i >> 6, c = i & 63;
        g_featDT[((size_t)b * NPIX + n0 + nn) * CH + c] = tile[c][nn];
    }
}

// ---------------- K2: PAM flash attention (f32x2, 2 queries/thread) ----------------
// grid (32, 8), block 128. Thread = (query pair, channel half).
// Each V LDS.128 now feeds 4 FFMA2 (2 queries) -> L1 pressure halved vs R2.
__global__ void __launch_bounds__(128) k2_pam(const float* __restrict__ x,
                                              const float* __restrict__ alpha) {
    __shared__ float Ks[8][128];    // [dim][key]
    __shared__ float Vs[128][64];   // [key][channel]
    const int t = threadIdx.x;
    const int b = blockIdx.y;
    const int n0 = blockIdx.x * 128;
    const int qi = t & 63;          // query pair index
    const int chalf = t >> 6;       // channel half (0: ch 0-31, 1: ch 32-63)
    const int nq = n0 + qi * 2;     // first of the two queries

    u64 q2[8];
#pragma unroll
    for (int d = 0; d < 8; d++) {
        const float* fp = g_featB + (size_t)(b * 8 + d) * NPIX + nq;
        q2[d] = pk2(fp[0], fp[1]);  // (q0, q1) packed
    }

    u64 acc0[16], acc1[16];         // per-query, 8 quads = 32 channels each
#pragma unroll
    for (int i = 0; i < 16; i++) { acc0[i] = 0ull; acc1[i] = 0ull; }
    float ssum0 = 0.f, ssum1 = 0.f;

    const float4* fc4 = (const float4*)(g_featC + (size_t)b * 8 * NPIX);
    const float4* fdt4 = (const float4*)(g_featDT + (size_t)b * NPIX * CH);

    for (int mc = 0; mc < 32; mc++) {
        const int m04 = mc * 32;    // chunk start, float4 units over keys
        const int m0 = mc * 128;    // chunk start, key units
#pragma unroll
        for (int k = 0; k < 2; k++) {  // K tile: 8x128 = 256 float4
            int i = t + 128 * k;
            int d = i >> 5, col = i & 31;
            ((float4*)Ks[d])[col] = fc4[d * 1024 + m04 + col];
        }
#pragma unroll
        for (int k = 0; k < 16; k++) { // V tile: 128x64 = 2048 float4
            int i = t + 128 * k;
            int row = i >> 4, cq = i & 15;
            ((float4*)Vs[row])[cq] = fdt4[(size_t)(m0 + row) * 16 + cq];
        }
        __syncthreads();

        for (int g = 0; g < 32; g++) {  // 4 keys per group
            float4 Kq[8];
#pragma unroll
            for (int d = 0; d < 8; d++) Kq[d] = ((const float4*)Ks[d])[g];

            u64 lp[4] = {0ull, 0ull, 0ull, 0ull};
#pragma unroll
            for (int d = 0; d < 8; d++) {
                lp[0] = ffma2(q2[d], pk2(Kq[d].x, Kq[d].x), lp[0]);
                lp[1] = ffma2(q2[d], pk2(Kq[d].y, Kq[d].y), lp[1]);
                lp[2] = ffma2(q2[d], pk2(Kq[d].z, Kq[d].z), lp[2]);
                lp[3] = ffma2(q2[d], pk2(Kq[d].w, Kq[d].w), lp[3]);
            }
#pragma unroll
            for (int j = 0; j < 4; j++) {
                float l0, l1;
                upk2(lp[j], l0, l1);
                float p0 = __expf(l0), p1 = __expf(l1);
                ssum0 += p0; ssum1 += p1;
                u64 P0 = pk2(p0, p0), P1 = pk2(p1, p1);
                const float4* vp = (const float4*)&Vs[4 * g + j][chalf * 32];
#pragma unroll
                for (int cq = 0; cq < 8; cq++) {
                    V4 vv; vv.f = vp[cq];
                    acc0[2 * cq]     = ffma2(P0, vv.u[0], acc0[2 * cq]);
                    acc0[2 * cq + 1] = ffma2(P0, vv.u[1], acc0[2 * cq + 1]);
                    acc1[2 * cq]     = ffma2(P1, vv.u[0], acc1[2 * cq]);
                    acc1[2 * cq + 1] = ffma2(P1, vv.u[1], acc1[2 * cq + 1]);
                }
            }
        }
        __syncthreads();
    }

    const float al = alpha[0];
    const float sc0 = al / ssum0;
    const float sc1 = al / ssum1;
#pragma unroll
    for (int i = 0; i < 16; i++) {
        float a0, a1, b0, b1;
        upk2(acc0[i], a0, a1);
        upk2(acc1[i], b0, b1);
        int c = chalf * 32 + 2 * i;   // channels c, c+1
        size_t i00 = (size_t)(b * CH + c) * NPIX + nq;
        g_xa[i00]            = fmaf(sc0, a0, x[i00]);
        g_xa[i00 + NPIX]     = fmaf(sc0, a1, x[i00 + NPIX]);
        g_xa[i00 + 1]        = fmaf(sc1, b0, x[i00 + 1]);
        g_xa[i00 + NPIX + 1] = fmaf(sc1, b1, x[i00 + NPIX + 1]);
    }
}

// ---------------- K3: CAM Gram matrix partials ----------------
__global__ void k3_att() {
    __shared__ float Xs[64][129];
    const int t = threadIdx.x;
    const int b = blockIdx.x;
    const int s = blockIdx.y;
    const int tx = t & 15, ty = t >> 4;

    float a4[4][4];
#pragma unroll
    for (int i = 0; i < 4; i++)
#pragma unroll
        for (int j = 0; j < 4; j++) a4[i][j] = 0.f;

    for (int chunk = 0; chunk < 2; chunk++) {
        const int n0 = s * 256 + chunk * 128;
        for (int i = t; i < 64 * 128; i += 256) {
            int c = i >> 7, col = i & 127;
            Xs[c][col] = g_xa[(size_t)(b * CH + c) * NPIX + n0 + col];
        }
        __syncthreads();
        for (int nn = 0; nn < 128; nn++) {
            float av[4], bv[4];
#pragma unroll
            for (int i = 0; i < 4; i++) av[i] = Xs[ty * 4 + i][nn];
#pragma unroll
            for (int j = 0; j < 4; j++) bv[j] = Xs[tx * 4 + j][nn];
#pragma unroll
            for (int i = 0; i < 4; i++)
#pragma unroll
                for (int j = 0; j < 4; j++) a4[i][j] = fmaf(av[i], bv[j], a4[i][j]);
        }
        __syncthreads();
    }
#pragma unroll
    for (int i = 0; i < 4; i++)
#pragma unroll
        for (int j = 0; j < 4; j++)
            g_attPart[(((size_t)s * BATCH + b) * CH + ty * 4 + i) * CH + tx * 4 + j] = a4[i][j];
}

// ---------------- K3b: reduce partials + CAM softmax (parallel) ----------------
__global__ void k3b_softmax() {
    const int c = blockIdx.x;
    const int b = blockIdx.y;
    const int d = threadIdx.x;
    const int lane = d & 31, warp = d >> 5;

    float s = 0.f;
#pragma unroll
    for (int sp = 0; sp < 16; sp++)
        s += g_attPart[(((size_t)sp * BATCH + b) * CH + c) * CH + d];

    float mn = s;
#pragma unroll
    for (int off = 16; off > 0; off >>= 1)
        mn = fminf(mn, __shfl_xor_sync(0xFFFFFFFFu, mn, off));
    __shared__ float sm2[2], ss2[2];
    if (lane == 0) sm2[warp] = mn;
    __syncthreads();
    mn = fminf(sm2[0], sm2[1]);

    float p = __expf(mn - s);
    float ps = p;
#pragma unroll
    for (int off = 16; off > 0; off >>= 1)
        ps += __shfl_xor_sync(0xFFFFFFFFu, ps, off);
    if (lane == 0) ss2[warp] = ps;
    __syncthreads();
    const float inv = 1.f / (ss2[0] + ss2[1]);
    g_attW[((size_t)b * CH + c) * CH + d] = p * inv;
}

// ---------------- K4: CAM apply + beta residual ----------------
__global__ void k4_cam(const float* __restrict__ beta) {
    __shared__ float Xs[64][64];
    __shared__ float Ws[64][64];
    const int t = threadIdx.x;
    const int b = blockIdx.y;
    const int n0 = blockIdx.x * 64;

    for (int i = t; i < 64 * 64; i += 256) {
        int c = i >> 6, col = i & 63;
        Xs[c][col] = g_xa[(size_t)(b * CH + c) * NPIX + n0 + col];
        ((float*)Ws)[i] = g_attW[(size_t)b * CH * CH + i];
    }
    __syncthreads();

    const int tx = t & 7, ty = t >> 3;
    float acc[2][8];
#pragma unroll
    for (int i = 0; i < 2; i++)
#pragma unroll
        for (int j = 0; j < 8; j++) acc[i][j] = 0.f;

    for (int d = 0; d < 64; d++) {
        float w0 = Ws[ty * 2 + 0][d];
        float w1 = Ws[ty * 2 + 1][d];
        float xv[8];
#pragma unroll
        for (int j = 0; j < 8; j++) xv[j] = Xs[d][tx * 8 + j];
#pragma unroll
        for (int j = 0; j < 8; j++) {
            acc[0][j] = fmaf(w0, xv[j], acc[0][j]);
            acc[1][j] = fmaf(w1, xv[j], acc[1][j]);
        }
    }
    const float be = beta[0];
#pragma unroll
    for (int i = 0; i < 2; i++) {
        int c = ty * 2 + i;
#pragma unroll
        for (int j = 0; j < 8; j++) {
            int nn = tx * 8 + j;
            g_xb[(size_t)(b * CH + c) * NPIX + n0 + nn] = fmaf(be, acc[i][j], Xs[c][nn]);
        }
    }
}

// ---------------- K5w: duplicate conv weights to float2 ----------------
__global__ void k5w_dup(const float* __restrict__ cw) {
    int i = blockIdx.x * 256 + threadIdx.x;
    if (i < 128 * 576) {
        float w = cw[i];
        g_cw2[i] = make_float2(w, w);
    }
}

// ---------------- K5: conv3x3 (64->128), f32x2, pad 1 ----------------
__global__ void __launch_bounds__(256) k5_conv(const float* __restrict__ cb) {
    __shared__ float In[4][34][34];
    __shared__ float2 Wt2[4 * 576];
    const int t = threadIdx.x;
    const int tile = blockIdx.x;
    const int ocg = blockIdx.y;
    const int b = blockIdx.z;
    const int h0 = (tile >> 1) * 32;
    const int w0 = (tile & 1) * 32;
    const int tx = t & 15, ty = t >> 4;

    for (int i = t; i < 2304; i += 256) Wt2[i] = g_cw2[(size_t)ocg * 2304 + i];

    u64 acc2[4][2];
#pragma unroll
    for (int o = 0; o < 4; o++) { acc2[o][0] = 0ull; acc2[o][1] = 0ull; }

    for (int cc = 0; cc < 16; cc++) {
        __syncthreads();
        for (int i = t; i < 4 * 34 * 34; i += 256) {
            int ic = i / 1156;
            int rem = i - ic * 1156;
            int r = rem / 34, cl = rem - r * 34;
            int gh = h0 + r - 1, gw = w0 + cl - 1;
            float v = 0.f;
            if (gh >= 0 && gh < 64 && gw >= 0 && gw < 64)
                v = g_xb[(size_t)(b * CH + cc * 4 + ic) * NPIX + gh * 64 + gw];
            In[ic][r][cl] = v;
        }
        __syncthreads();
#pragma unroll
        for (int ic = 0; ic < 4; ic++) {
            u64 xa[4], xb2[4], xm[4];
#pragma unroll
            for (int dy = 0; dy < 4; dy++) {
                F2 A, Bv;
                A.f  = *(const float2*)&In[ic][ty * 2 + dy][tx * 2];
                Bv.f = *(const float2*)&In[ic][ty * 2 + dy][tx * 2 + 2];
                xa[dy] = A.u;
                xb2[dy] = Bv.u;
                xm[dy] = pk2(A.f.y, Bv.f.x);
            }
            const int icf = cc * 4 + ic;
#pragma unroll
            for (int o = 0; o < 4; o++) {
                const float2* wp = &Wt2[o * 576 + icf * 9];
#pragma unroll
                for (int ky = 0; ky < 3; ky++)
#pragma unroll
                    for (int kx = 0; kx < 3; kx++) {
                        F2 w; w.f = wp[ky * 3 + kx];
                        const u64* xrow = (kx == 0) ? xa : (kx == 1) ? xm : xb2;
                        acc2[o][0] = ffma2(w.u, xrow[ky + 0], acc2[o][0]);
                        acc2[o][1] = ffma2(w.u, xrow[ky + 1], acc2[o][1]);
                    }
            }
        }
    }
#pragma unroll
    for (int o = 0; o < 4; o++) {
        const int oc = ocg * 4 + o;
        const float bs = cb[oc];
#pragma unroll
        for (int a = 0; a < 2; a++) {
            float r0, r1;
            upk2(acc2[o][a], r0, r1);
            int hh = h0 + ty * 2 + a, ww = w0 + tx * 2;
            size_t base = (size_t)(b * 128 + oc) * NPIX + hh * 64 + ww;
            g_conv[base] = r0 + bs;
            g_conv[base + 1] = r1 + bs;
        }
    }
}

// ---------------- K5b: BN stats per channel ----------------
__global__ void k5b_bn(const float* __restrict__ gamma, const float* __restrict__ bbeta) {
    const int oc = blockIdx.x;
    const int t = threadIdx.x;
    float s = 0.f, sq = 0.f;
    for (int i = t; i < BATCH * NPIX; i += 256) {
        int bb = i >> 12, hw = i & 4095;
        float v = g_conv[(size_t)(bb * 128 + oc) * NPIX + hw];
        s += v;
        sq += v * v;
    }
    __shared__ float rs[256], rq[256];
    rs[t] = s; rq[t] = sq;
    __syncthreads();
    for (int st = 128; st > 0; st >>= 1) {
        if (t < st) { rs[t] += rs[t + st]; rq[t] += rq[t + st]; }
        __syncthreads();
    }
    if (t == 0) {
        const float invN = 1.f / (BATCH * NPIX);
        float mean = rs[0] * invN;
        float var = rq[0] * invN - mean * mean;
        float sc = gamma[oc] * rsqrtf(var + 1e-5f);
        g_bnScale[oc] = sc;
        g_bnShift[oc] = bbeta[oc] - mean * sc;
    }
}

// ---------------- K7: BN apply + ReLU + maxpool(2,2, h-pad 1) ----------------
__global__ void k7_pool(float* __restrict__ out) {
    const int idx = blockIdx.x * 256 + threadIdx.x;
    const int TOT = BATCH * 128 * 33 * 32;
    if (idx >= TOT) return;
    int pw = idx & 31;
    int tmp = idx >> 5;
    int ph = tmp % 33; tmp /= 33;
    int oc = tmp & 127;
    int b = tmp >> 7;

    const float sc = g_bnScale[oc], sh = g_bnShift[oc];
    const float* base = g_conv + (size_t)(b * 128 + oc) * NPIX;
    const int w1 = pw * 2;
    const int h1 = ph * 2 - 1;
    float m = -3.4e38f;
#pragma unroll
    for (int k = 0; k < 2; k++) {
        int hh = h1 + k;
        if (hh < 0 || hh >= 64) continue;
        m = fmaxf(m, fmaf(base[hh * 64 + w1], sc, sh));
        m = fmaxf(m, fmaf(base[hh * 64 + w1 + 1], sc, sh));
    }
    out[idx] = fmaxf(m, 0.f);
}

// ---------------- launch ----------------
extern "C" void kernel_launch(void* const* d_in, const int* in_sizes, int n_in,
                              void* d_out, int out_size) {
    const float* x     = (const float*)d_in[0];
    const float* wb    = (const float*)d_in[1];
    const float* bb    = (const float*)d_in[2];
    const float* wc    = (const float*)d_in[3];
    const float* bc    = (const float*)d_in[4];
    const float* wd    = (const float*)d_in[5];
    const float* bd    = (const float*)d_in[6];
    const float* alpha = (const float*)d_in[7];
    const float* beta  = (const float*)d_in[8];
    const float* cw    = (const float*)d_in[9];
    const float* cb    = (const float*)d_in[10];
    const float* gamma = (const float*)d_in[11];
    const float* bbeta = (const float*)d_in[12];
    float* out = (float*)d_out;

    k5w_dup<<<(128 * 576 + 255) / 256, 256>>>(cw);
    k1_proj<<<dim3(16, 5, 8), 256>>>(x, wb, bb, wc, bc, wd, bd);
    k1t_transpose<<<dim3(64, 8), 256>>>();
    k2_pam<<<dim3(32, 8), 128>>>(x, alpha);
    k3_att<<<dim3(8, 16), 256>>>();
    k3b_softmax<<<dim3(64, 8), 64>>>();
    k4_cam<<<dim3(64, 8), 256>>>(beta);
    k5_conv<<<dim3(4, 32, 8), 256>>>(cb);
    k5b_bn<<<128, 256>>>(gamma, bbeta);
    const int tot = BATCH * 128 * 33 * 32;
    k7_pool<<<(tot + 255) / 256, 256>>>(out);
}

// round 5
// speedup vs baseline: 1.2888x; 1.1152x over previous
#include <cuda_runtime.h>
#include <math.h>

#define NPIX 4096
#define BATCH 8
#define CH 64
#define KSPLIT 4

typedef unsigned long long u64;

// ---------------- f32x2 helpers (Blackwell packed fp32) ----------------
__device__ __forceinline__ u64 pk2(float lo, float hi) {
    u64 r; asm("mov.b64 %0, {%1, %2};" : "=l"(r) : "f"(lo), "f"(hi)); return r;
}
__device__ __forceinline__ void upk2(u64 v, float& lo, float& hi) {
    asm("mov.b64 {%0, %1}, %2;" : "=f"(lo), "=f"(hi) : "l"(v));
}
__device__ __forceinline__ u64 ffma2(u64 a, u64 b, u64 c) {
    u64 d; asm("fma.rn.f32x2 %0, %1, %2, %3;" : "=l"(d) : "l"(a), "l"(b), "l"(c)); return d;
}
union V4 { float4 f; u64 u[2]; };
union F2 { float2 f; u64 u; };

// ---------------- scratch (device globals) ----------------
__device__ float g_featB[BATCH * 8 * NPIX];
__device__ float g_featC[BATCH * 8 * NPIX];
__device__ float g_featD[BATCH * CH * NPIX];
__device__ float g_featDT[BATCH * NPIX * CH];       // key-major V
__device__ float g_pacc[KSPLIT * BATCH * CH * NPIX]; // split-K partial numerators
__device__ float g_pssum[KSPLIT * BATCH * NPIX];     // split-K partial denominators
__device__ float g_scale[BATCH * NPIX];              // alpha / total denominator
__device__ float g_xa[BATCH * CH * NPIX];
__device__ float g_xb[BATCH * CH * NPIX];
__device__ float g_attPart[16 * BATCH * CH * CH];
__device__ float g_attW[BATCH * CH * CH];
__device__ float g_conv[BATCH * 128 * NPIX];
__device__ float g_bnScale[128];
__device__ float g_bnShift[128];
__device__ float2 g_cw2[128 * 576];                  // duplicated conv weights

// ---------------- K1: fused 1x1 projections ----------------
__global__ void k1_proj(const float* __restrict__ x,
                        const float* __restrict__ wb, const float* __restrict__ bb,
                        const float* __restrict__ wc, const float* __restrict__ bc,
                        const float* __restrict__ wd, const float* __restrict__ bd) {
    __shared__ float Ws[16][64];
    __shared__ float Bs[16];
    const int t = threadIdx.x;
    const int og0 = blockIdx.y * 16;
    const int b = blockIdx.z;

    for (int i = t; i < 16 * 64; i += 256) {
        int o = og0 + (i >> 6), c = i & 63;
        float w;
        if (o < 8) w = wb[o * 64 + c];
        else if (o < 16) w = wc[(o - 8) * 64 + c];
        else w = wd[(o - 16) * 64 + c];
        Ws[i >> 6][c] = w;
    }
    if (t < 16) {
        int o = og0 + t;
        Bs[t] = (o < 8) ? bb[o] : (o < 16) ? bc[o - 8] : bd[o - 16];
    }
    __syncthreads();

    const int n = blockIdx.x * 256 + t;
    const float* xp = x + (size_t)b * CH * NPIX + n;
    float acc[16];
#pragma unroll
    for (int i = 0; i < 16; i++) acc[i] = Bs[i];

    for (int c = 0; c < 64; c += 4) {
        float x0 = xp[(size_t)(c + 0) * NPIX];
        float x1 = xp[(size_t)(c + 1) * NPIX];
        float x2 = xp[(size_t)(c + 2) * NPIX];
        float x3 = xp[(size_t)(c + 3) * NPIX];
#pragma unroll
        for (int o = 0; o < 16; o++) {
            float4 w = *(const float4*)&Ws[o][c];
            acc[o] = fmaf(w.x, x0, fmaf(w.y, x1, fmaf(w.z, x2, fmaf(w.w, x3, acc[o]))));
        }
    }
#pragma unroll
    for (int o = 0; o < 16; o++) {
        int og = og0 + o;
        if (og < 8)       g_featB[(size_t)(b * 8 + og) * NPIX + n] = acc[o];
        else if (og < 16) g_featC[(size_t)(b * 8 + og - 8) * NPIX + n] = acc[o];
        else              g_featD[(size_t)(b * CH + og - 16) * NPIX + n] = acc[o];
    }
}

// ---------------- K1t: transpose featD [b][c][n] -> featDT [b][n][c] ----------------
__global__ void k1t_transpose() {
    __shared__ float tile[64][65];
    const int t = threadIdx.x;
    const int b = blockIdx.y;
    const int n0 = blockIdx.x * 64;
#pragma unroll
    for (int k = 0; k < 16; k++) {
        int i = t + 256 * k;
        int c = i >> 6, nn = i & 63;
        tile[c][nn] = g_featD[(size_t)(b * CH + c) * NPIX + n0 + nn];
    }
    __syncthreads();
#pragma unroll
    for (int k = 0; k < 16; k++) {
        int i = t + 256 * k;
        int nn = i >> 6, c = i & 63;
        g_featDT[((size_t)b * NPIX + n0 + nn) * CH + c] = tile[c][nn];
    }
}

// ---------------- K2: PAM flash attention, split-K partials ----------------
// grid (32 qtiles, KSPLIT, 8 batch), block 128.
// Thread = (query pair, channel half); block covers 1024 keys.
__global__ void __launch_bounds__(128) k2_pam() {
    __shared__ float Ks[8][128];    // [dim][key]
    __shared__ float Vs[128][64];   // [key][channel]
    const int t = threadIdx.x;
    const int ks = blockIdx.y;
    const int b = blockIdx.z;
    const int n0 = blockIdx.x * 128;
    const int qi = t & 63;          // query pair index
    const int chalf = t >> 6;       // channel half
    const int nq = n0 + qi * 2;

    u64 q2[8];
#pragma unroll
    for (int d = 0; d < 8; d++) {
        const float* fp = g_featB + (size_t)(b * 8 + d) * NPIX + nq;
        q2[d] = pk2(fp[0], fp[1]);
    }

    u64 acc0[16], acc1[16];
#pragma unroll
    for (int i = 0; i < 16; i++) { acc0[i] = 0ull; acc1[i] = 0ull; }
    float ssum0 = 0.f, ssum1 = 0.f;

    const float4* fc4 = (const float4*)(g_featC + (size_t)b * 8 * NPIX);
    const float4* fdt4 = (const float4*)(g_featDT + (size_t)b * NPIX * CH);

    const int mc0 = ks * (32 / KSPLIT);
    for (int mc = mc0; mc < mc0 + 32 / KSPLIT; mc++) {
        const int m04 = mc * 32;
        const int m0 = mc * 128;
#pragma unroll
        for (int k = 0; k < 2; k++) {  // K tile
            int i = t + 128 * k;
            int d = i >> 5, col = i & 31;
            ((float4*)Ks[d])[col] = fc4[d * 1024 + m04 + col];
        }
#pragma unroll
        for (int k = 0; k < 16; k++) { // V tile
            int i = t + 128 * k;
            int row = i >> 4, cq = i & 15;
            ((float4*)Vs[row])[cq] = fdt4[(size_t)(m0 + row) * 16 + cq];
        }
        __syncthreads();

        for (int g = 0; g < 32; g++) {
            float4 Kq[8];
#pragma unroll
            for (int d = 0; d < 8; d++) Kq[d] = ((const float4*)Ks[d])[g];

            u64 lp[4] = {0ull, 0ull, 0ull, 0ull};
#pragma unroll
            for (int d = 0; d < 8; d++) {
                lp[0] = ffma2(q2[d], pk2(Kq[d].x, Kq[d].x), lp[0]);
                lp[1] = ffma2(q2[d], pk2(Kq[d].y, Kq[d].y), lp[1]);
                lp[2] = ffma2(q2[d], pk2(Kq[d].z, Kq[d].z), lp[2]);
                lp[3] = ffma2(q2[d], pk2(Kq[d].w, Kq[d].w), lp[3]);
            }
#pragma unroll
            for (int j = 0; j < 4; j++) {
                float l0, l1;
                upk2(lp[j], l0, l1);
                float p0 = __expf(l0), p1 = __expf(l1);
                ssum0 += p0; ssum1 += p1;
                u64 P0 = pk2(p0, p0), P1 = pk2(p1, p1);
                const float4* vp = (const float4*)&Vs[4 * g + j][chalf * 32];
#pragma unroll
                for (int cq = 0; cq < 8; cq++) {
                    V4 vv; vv.f = vp[cq];
                    acc0[2 * cq]     = ffma2(P0, vv.u[0], acc0[2 * cq]);
                    acc0[2 * cq + 1] = ffma2(P0, vv.u[1], acc0[2 * cq + 1]);
                    acc1[2 * cq]     = ffma2(P1, vv.u[0], acc1[2 * cq]);
                    acc1[2 * cq + 1] = ffma2(P1, vv.u[1], acc1[2 * cq + 1]);
                }
            }
        }
        __syncthreads();
    }

    if (chalf == 0) {
        float* ps = g_pssum + ((size_t)ks * BATCH + b) * NPIX + nq;
        ps[0] = ssum0;
        ps[1] = ssum1;
    }
    float* pa = g_pacc + ((size_t)ks * BATCH + b) * CH * NPIX;
#pragma unroll
    for (int i = 0; i < 16; i++) {
        float a0, a1, b0, b1;
        upk2(acc0[i], a0, a1);
        upk2(acc1[i], b0, b1);
        int c = chalf * 32 + 2 * i;
        size_t i00 = (size_t)c * NPIX + nq;
        pa[i00] = a0;
        pa[i00 + NPIX] = a1;
        pa[i00 + 1] = b0;
        pa[i00 + NPIX + 1] = b1;
    }
}

// ---------------- K2s: combine denominators -> scale ----------------
__global__ void k2s_scale(const float* __restrict__ alpha) {
    const int idx = blockIdx.x * 256 + threadIdx.x;  // b*NPIX+n
    if (idx >= BATCH * NPIX) return;
    float s = 0.f;
#pragma unroll
    for (int k = 0; k < KSPLIT; k++) s += g_pssum[(size_t)k * BATCH * NPIX + idx];
    g_scale[idx] = alpha[0] / s;
}

// ---------------- K2r: combine numerators + residual ----------------
__global__ void k2r_reduce(const float* __restrict__ x) {
    const int idx4 = blockIdx.x * 256 + threadIdx.x;      // float4 index
    const int TOT4 = BATCH * CH * NPIX / 4;
    if (idx4 >= TOT4) return;
    const int idx = idx4 * 4;
    const int n = idx & (NPIX - 1);
    const int b = idx / (CH * NPIX);

    float4 a = *(const float4*)&g_pacc[idx];
#pragma unroll
    for (int k = 1; k < KSPLIT; k++) {
        float4 p = *(const float4*)&g_pacc[(size_t)k * BATCH * CH * NPIX + idx];
        a.x += p.x; a.y += p.y; a.z += p.z; a.w += p.w;
    }
    float4 sc = *(const float4*)&g_scale[b * NPIX + n];
    float4 xv = *(const float4*)&x[idx];
    float4 o;
    o.x = fmaf(sc.x, a.x, xv.x);
    o.y = fmaf(sc.y, a.y, xv.y);
    o.z = fmaf(sc.z, a.z, xv.z);
    o.w = fmaf(sc.w, a.w, xv.w);
    *(float4*)&g_xa[idx] = o;
}

// ---------------- K3: CAM Gram matrix partials ----------------
__global__ void k3_att() {
    __shared__ float Xs[64][129];
    const int t = threadIdx.x;
    const int b = blockIdx.x;
    const int s = blockIdx.y;
    const int tx = t & 15, ty = t >> 4;

    float a4[4][4];
#pragma unroll
    for (int i = 0; i < 4; i++)
#pragma unroll
        for (int j = 0; j < 4; j++) a4[i][j] = 0.f;

    for (int chunk = 0; chunk < 2; chunk++) {
        const int n0 = s * 256 + chunk * 128;
        for (int i = t; i < 64 * 128; i += 256) {
            int c = i >> 7, col = i & 127;
            Xs[c][col] = g_xa[(size_t)(b * CH + c) * NPIX + n0 + col];
        }
        __syncthreads();
        for (int nn = 0; nn < 128; nn++) {
            float av[4], bv[4];
#pragma unroll
            for (int i = 0; i < 4; i++) av[i] = Xs[ty * 4 + i][nn];
#pragma unroll
            for (int j = 0; j < 4; j++) bv[j] = Xs[tx * 4 + j][nn];
#pragma unroll
            for (int i = 0; i < 4; i++)
#pragma unroll
                for (int j = 0; j < 4; j++) a4[i][j] = fmaf(av[i], bv[j], a4[i][j]);
        }
        __syncthreads();
    }
#pragma unroll
    for (int i = 0; i < 4; i++)
#pragma unroll
        for (int j = 0; j < 4; j++)
            g_attPart[(((size_t)s * BATCH + b) * CH + ty * 4 + i) * CH + tx * 4 + j] = a4[i][j];
}

// ---------------- K3b: reduce partials + CAM softmax ----------------
__global__ void k3b_softmax() {
    const int c = blockIdx.x;
    const int b = blockIdx.y;
    const int d = threadIdx.x;
    const int lane = d & 31, warp = d >> 5;

    float s = 0.f;
#pragma unroll
    for (int sp = 0; sp < 16; sp++)
        s += g_attPart[(((size_t)sp * BATCH + b) * CH + c) * CH + d];

    float mn = s;
#pragma unroll
    for (int off = 16; off > 0; off >>= 1)
        mn = fminf(mn, __shfl_xor_sync(0xFFFFFFFFu, mn, off));
    __shared__ float sm2[2], ss2[2];
    if (lane == 0) sm2[warp] = mn;
    __syncthreads();
    mn = fminf(sm2[0], sm2[1]);

    float p = __expf(mn - s);
    float ps = p;
#pragma unroll
    for (int off = 16; off > 0; off >>= 1)
        ps += __shfl_xor_sync(0xFFFFFFFFu, ps, off);
    if (lane == 0) ss2[warp] = ps;
    __syncthreads();
    const float inv = 1.f / (ss2[0] + ss2[1]);
    g_attW[((size_t)b * CH + c) * CH + d] = p * inv;
}

// ---------------- K4: CAM apply + beta residual ----------------
__global__ void k4_cam(const float* __restrict__ beta) {
    __shared__ float Xs[64][64];
    __shared__ float Ws[64][64];
    const int t = threadIdx.x;
    const int b = blockIdx.y;
    const int n0 = blockIdx.x * 64;

    for (int i = t; i < 64 * 64; i += 256) {
        int c = i >> 6, col = i & 63;
        Xs[c][col] = g_xa[(size_t)(b * CH + c) * NPIX + n0 + col];
        ((float*)Ws)[i] = g_attW[(size_t)b * CH * CH + i];
    }
    __syncthreads();

    const int tx = t & 7, ty = t >> 3;
    float acc[2][8];
#pragma unroll
    for (int i = 0; i < 2; i++)
#pragma unroll
        for (int j = 0; j < 8; j++) acc[i][j] = 0.f;

    for (int d = 0; d < 64; d++) {
        float w0 = Ws[ty * 2 + 0][d];
        float w1 = Ws[ty * 2 + 1][d];
        float xv[8];
#pragma unroll
        for (int j = 0; j < 8; j++) xv[j] = Xs[d][tx * 8 + j];
#pragma unroll
        for (int j = 0; j < 8; j++) {
            acc[0][j] = fmaf(w0, xv[j], acc[0][j]);
            acc[1][j] = fmaf(w1, xv[j], acc[1][j]);
        }
    }
    const float be = beta[0];
#pragma unroll
    for (int i = 0; i < 2; i++) {
        int c = ty * 2 + i;
#pragma unroll
        for (int j = 0; j < 8; j++) {
            int nn = tx * 8 + j;
            g_xb[(size_t)(b * CH + c) * NPIX + n0 + nn] = fmaf(be, acc[i][j], Xs[c][nn]);
        }
    }
}

// ---------------- K5w: duplicate conv weights to float2 ----------------
__global__ void k5w_dup(const float* __restrict__ cw) {
    int i = blockIdx.x * 256 + threadIdx.x;
    if (i < 128 * 576) {
        float w = cw[i];
        g_cw2[i] = make_float2(w, w);
    }
}

// ---------------- K5: conv3x3 (64->128), f32x2, pad 1 ----------------
__global__ void __launch_bounds__(256) k5_conv(const float* __restrict__ cb) {
    __shared__ float In[4][34][34];
    __shared__ float2 Wt2[4 * 576];
    const int t = threadIdx.x;
    const int tile = blockIdx.x;
    const int ocg = blockIdx.y;
    const int b = blockIdx.z;
    const int h0 = (tile >> 1) * 32;
    const int w0 = (tile & 1) * 32;
    const int tx = t & 15, ty = t >> 4;

    for (int i = t; i < 2304; i += 256) Wt2[i] = g_cw2[(size_t)ocg * 2304 + i];

    u64 acc2[4][2];
#pragma unroll
    for (int o = 0; o < 4; o++) { acc2[o][0] = 0ull; acc2[o][1] = 0ull; }

    for (int cc = 0; cc < 16; cc++) {
        __syncthreads();
        for (int i = t; i < 4 * 34 * 34; i += 256) {
            int ic = i / 1156;
            int rem = i - ic * 1156;
            int r = rem / 34, cl = rem - r * 34;
            int gh = h0 + r - 1, gw = w0 + cl - 1;
            float v = 0.f;
            if (gh >= 0 && gh < 64 && gw >= 0 && gw < 64)
                v = g_xb[(size_t)(b * CH + cc * 4 + ic) * NPIX + gh * 64 + gw];
            In[ic][r][cl] = v;
        }
        __syncthreads();
#pragma unroll
        for (int ic = 0; ic < 4; ic++) {
            u64 xa[4], xb2[4], xm[4];
#pragma unroll
            for (int dy = 0; dy < 4; dy++) {
                F2 A, Bv;
                A.f  = *(const float2*)&In[ic][ty * 2 + dy][tx * 2];
                Bv.f = *(const float2*)&In[ic][ty * 2 + dy][tx * 2 + 2];
                xa[dy] = A.u;
                xb2[dy] = Bv.u;
                xm[dy] = pk2(A.f.y, Bv.f.x);
            }
            const int icf = cc * 4 + ic;
#pragma unroll
            for (int o = 0; o < 4; o++) {
                const float2* wp = &Wt2[o * 576 + icf * 9];
#pragma unroll
                for (int ky = 0; ky < 3; ky++)
#pragma unroll
                    for (int kx = 0; kx < 3; kx++) {
                        F2 w; w.f = wp[ky * 3 + kx];
                        const u64* xrow = (kx == 0) ? xa : (kx == 1) ? xm : xb2;
                        acc2[o][0] = ffma2(w.u, xrow[ky + 0], acc2[o][0]);
                        acc2[o][1] = ffma2(w.u, xrow[ky + 1], acc2[o][1]);
                    }
            }
        }
    }
#pragma unroll
    for (int o = 0; o < 4; o++) {
        const int oc = ocg * 4 + o;
        const float bs = cb[oc];
#pragma unroll
        for (int a = 0; a < 2; a++) {
            float r0, r1;
            upk2(acc2[o][a], r0, r1);
            int hh = h0 + ty * 2 + a, ww = w0 + tx * 2;
            size_t base = (size_t)(b * 128 + oc) * NPIX + hh * 64 + ww;
            g_conv[base] = r0 + bs;
            g_conv[base + 1] = r1 + bs;
        }
    }
}

// ---------------- K5b: BN stats per channel ----------------
__global__ void k5b_bn(const float* __restrict__ gamma, const float* __restrict__ bbeta) {
    const int oc = blockIdx.x;
    const int t = threadIdx.x;
    float s = 0.f, sq = 0.f;
    for (int i = t; i < BATCH * NPIX; i += 256) {
        int bb = i >> 12, hw = i & 4095;
        float v = g_conv[(size_t)(bb * 128 + oc) * NPIX + hw];
        s += v;
        sq += v * v;
    }
    __shared__ float rs[256], rq[256];
    rs[t] = s; rq[t] = sq;
    __syncthreads();
    for (int st = 128; st > 0; st >>= 1) {
        if (t < st) { rs[t] += rs[t + st]; rq[t] += rq[t + st]; }
        __syncthreads();
    }
    if (t == 0) {
        const float invN = 1.f / (BATCH * NPIX);
        float mean = rs[0] * invN;
        float var = rq[0] * invN - mean * mean;
        float sc = gamma[oc] * rsqrtf(var + 1e-5f);
        g_bnScale[oc] = sc;
        g_bnShift[oc] = bbeta[oc] - mean * sc;
    }
}

// ---------------- K7: BN apply + ReLU + maxpool(2,2, h-pad 1) ----------------
__global__ void k7_pool(float* __restrict__ out) {
    const int idx = blockIdx.x * 256 + threadIdx.x;
    const int TOT = BATCH * 128 * 33 * 32;
    if (idx >= TOT) return;
    int pw = idx & 31;
    int tmp = idx >> 5;
    int ph = tmp % 33; tmp /= 33;
    int oc = tmp & 127;
    int b = tmp >> 7;

    const float sc = g_bnScale[oc], sh = g_bnShift[oc];
    const float* base = g_conv + (size_t)(b * 128 + oc) * NPIX;
    const int w1 = pw * 2;
    const int h1 = ph * 2 - 1;
    float m = -3.4e38f;
#pragma unroll
    for (int k = 0; k < 2; k++) {
        int hh = h1 + k;
        if (hh < 0 || hh >= 64) continue;
        m = fmaxf(m, fmaf(base[hh * 64 + w1], sc, sh));
        m = fmaxf(m, fmaf(base[hh * 64 + w1 + 1], sc, sh));
    }
    out[idx] = fmaxf(m, 0.f);
}

// ---------------- launch ----------------
extern "C" void kernel_launch(void* const* d_in, const int* in_sizes, int n_in,
                              void* d_out, int out_size) {
    const float* x     = (const float*)d_in[0];
    const float* wb    = (const float*)d_in[1];
    const float* bb    = (const float*)d_in[2];
    const float* wc    = (const float*)d_in[3];
    const float* bc    = (const float*)d_in[4];
    const float* wd    = (const float*)d_in[5];
    const float* bd    = (const float*)d_in[6];
    const float* alpha = (const float*)d_in[7];
    const float* beta  = (const float*)d_in[8];
    const float* cw    = (const float*)d_in[9];
    const float* cb    = (const float*)d_in[10];
    const float* gamma = (const float*)d_in[11];
    const float* bbeta = (const float*)d_in[12];
    float* out = (float*)d_out;

    k5w_dup<<<(128 * 576 + 255) / 256, 256>>>(cw);
    k1_proj<<<dim3(16, 5, 8), 256>>>(x, wb, bb, wc, bc, wd, bd);
    k1t_transpose<<<dim3(64, 8), 256>>>();
    k2_pam<<<dim3(32, KSPLIT, 8), 128>>>();
    k2s_scale<<<(BATCH * NPIX + 255) / 256, 256>>>(alpha);
    k2r_reduce<<<(BATCH * CH * NPIX / 4 + 255) / 256, 256>>>(x);
    k3_att<<<dim3(8, 16), 256>>>();
    k3b_softmax<<<dim3(64, 8), 64>>>();
    k4_cam<<<dim3(64, 8), 256>>>(beta);
    k5_conv<<<dim3(4, 32, 8), 256>>>(cb);
    k5b_bn<<<128, 256>>>(gamma, bbeta);
    const int tot = BATCH * 128 * 33 * 32;
    k7_pool<<<(tot + 255) / 256, 256>>>(out);
}